// round 12
// baseline (speedup 1.0000x reference)
#include <cuda_runtime.h>
#include <cuda_fp16.h>
#include <math.h>
#include <stdint.h>

#define N_NODES 50000
#define N_EDGES 800000
#define F       128      // HEADS*HID
#define HEADS   4
#define HID     32
#define NEG_SLOPE 0.2f
#define MTILE   80       // 50000 = 625 * 80
#define CAP     96       // per-node edge bucket (deg ~ Poisson(16); P(>96) ~ 0)

// ---------------- device-global scratch (no allocations allowed) -------------
__device__ __align__(16) __half g_hh [N_NODES * F];   // h = x @ W (fp16)
__device__ __align__(16) __half g_xh [N_NODES * F];   // layer-1 input, fp16
__device__ __align__(16) __half g_x2h[N_NODES * F];   // layer-1 output, fp16
__device__ __align__(16) float  g_el [N_NODES * HEADS];
__device__ __align__(16) float  g_er [N_NODES * HEADS];
// B fragments, fp16, paired n-tiles (m16n8k16)
__device__ __align__(16) uint4  g_Bfrag[8 * 8 * 32];
__device__ unsigned g_cur[N_NODES];                   // zero-init; agg2 re-zeroes
__device__ int      g_csr_src[N_NODES * CAP];         // padded per-dst buckets

// ---------------- helpers -----------------------------------------------------
__device__ __forceinline__ unsigned pack_h2(float x0, float x1) {
    __half2 h = __floats2half2_rn(x0, x1);
    return *(unsigned*)&h;
}
__device__ __forceinline__ void mma_f16(float4& d,
                                        unsigned a0, unsigned a1, unsigned a2, unsigned a3,
                                        unsigned b0, unsigned b1) {
    asm volatile("mma.sync.aligned.m16n8k16.row.col.f32.f16.f16.f32 "
                 "{%0,%1,%2,%3}, {%4,%5,%6,%7}, {%8,%9}, {%0,%1,%2,%3};"
                 : "+f"(d.x), "+f"(d.y), "+f"(d.z), "+f"(d.w)
                 : "r"(a0), "r"(a1), "r"(a2), "r"(a3), "r"(b0), "r"(b1));
}
__device__ __forceinline__ void ldsm_x4(unsigned& a0, unsigned& a1, unsigned& a2, unsigned& a3,
                                        uint32_t addr) {
    asm volatile("ldmatrix.sync.aligned.m8n8.x4.shared.b16 {%0,%1,%2,%3}, [%4];"
                 : "=r"(a0), "=r"(a1), "=r"(a2), "=r"(a3) : "r"(addr));
}

// ---------------- fp32 -> fp16 convert (layer-1 input) ------------------------
__global__ void conv_half_kernel(const float* __restrict__ x) {
    int i = blockIdx.x * blockDim.x + threadIdx.x;
    if (i >= N_NODES * F / 4) return;
    float4 v = ((const float4*)x)[i];
    uint2 u;
    u.x = pack_h2(v.x, v.y); u.y = pack_h2(v.z, v.w);
    ((uint2*)g_xh)[i] = u;
}

// ---------------- padded-CSR scatter (single kernel, no hist/scan) ------------
__global__ void scatter_kernel(const int* __restrict__ src, const int* __restrict__ dst) {
    int e = blockIdx.x * blockDim.x + threadIdx.x;
    if (e >= N_EDGES) return;
    int d = dst[e];
    unsigned pos = atomicAdd(&g_cur[d], 1u);
    if (pos < CAP) g_csr_src[(size_t)d * CAP + pos] = src[e];
}

// ---------------- W -> fp16 fragment layout (m16n8k16, paired n-tiles) --------
__global__ void bfrag_kernel(const float* __restrict__ W) {
    int idx = blockIdx.x * blockDim.x + threadIdx.x;
    if (idx >= 8 * 8 * 32) return;
    int lane = idx & 31, p = (idx >> 5) & 7, kk = idx >> 8;
    int g = lane >> 2, tig = lane & 3;
    int k0 = kk * 16 + 2 * tig;
    int k1 = k0 + 8;
    int n0 = (2 * p) * 8 + g;
    int n1 = (2 * p + 1) * 8 + g;
    uint4 o;
    o.x = pack_h2(W[k0 * 128 + n0], W[(k0 + 1) * 128 + n0]);
    o.y = pack_h2(W[k1 * 128 + n0], W[(k1 + 1) * 128 + n0]);
    o.z = pack_h2(W[k0 * 128 + n1], W[(k0 + 1) * 128 + n1]);
    o.w = pack_h2(W[k1 * 128 + n1], W[(k1 + 1) * 128 + n1]);
    g_Bfrag[idx] = o;
}

// ---------------- tensor-core GEMM (fp16 A via ldmatrix) + fused el/er --------
#define XSTRIDE 136
__global__ __launch_bounds__(320) void gemm_mma_kernel(
        const __half* __restrict__ x,
        const float* __restrict__ al, const float* __restrict__ ar) {
    __shared__ __half xs[MTILE * XSTRIDE];
    const int tid = threadIdx.x, wid = tid >> 5, lane = tid & 31;
    const int g = lane >> 2, tig = lane & 3;
    const int base = blockIdx.x * MTILE;

    for (int q = tid; q < MTILE * 16; q += 320) {
        int row = q >> 4, c8 = q & 15;
        uint4 v = ((const uint4*)(x + (size_t)(base + row) * F))[c8];
        *(uint4*)&xs[row * XSTRIDE + c8 * 8] = v;
    }
    __syncthreads();

    const int warpM = wid >> 1, warpN = wid & 1;
    const int rowbase = warpM * 16;

    const int lrow = rowbase + ((lane >> 3) & 1) * 8 + (lane & 7);
    uint32_t abase = (uint32_t)__cvta_generic_to_shared(xs)
                   + lrow * (XSTRIDE * 2) + (lane >> 4) * 16;

    float4 acc[8];
    #pragma unroll
    for (int j = 0; j < 8; j++) acc[j] = make_float4(0.f, 0.f, 0.f, 0.f);

    #pragma unroll
    for (int kk = 0; kk < 8; kk++) {
        unsigned a0, a1, a2, a3;
        ldsm_x4(a0, a1, a2, a3, abase + kk * 32);
        const uint4* bp = g_Bfrag + (size_t)(kk * 8 + warpN * 4) * 32 + lane;
        #pragma unroll
        for (int jp = 0; jp < 4; jp++) {
            uint4 b = bp[jp * 32];
            mma_f16(acc[2 * jp + 0], a0, a1, a2, a3, b.x, b.y);
            mma_f16(acc[2 * jp + 1], a0, a1, a2, a3, b.z, b.w);
        }
    }

    // ---- epilogue: el/er + smem-staged coalesced h store ----
    const int r0 = base + rowbase + g, r1 = r0 + 8;
    float pel[2][2] = {{0.f,0.f},{0.f,0.f}};
    float per[2][2] = {{0.f,0.f},{0.f,0.f}};
    #pragma unroll
    for (int j = 0; j < 8; j++) {
        int col = warpN * 64 + j * 8 + 2 * tig;
        float al0 = al[col], al1 = al[col + 1];
        float ar0 = ar[col], ar1 = ar[col + 1];
        int hh = j >> 2;
        pel[hh][0] += acc[j].x * al0 + acc[j].y * al1;
        pel[hh][1] += acc[j].z * al0 + acc[j].w * al1;
        per[hh][0] += acc[j].x * ar0 + acc[j].y * ar1;
        per[hh][1] += acc[j].z * ar0 + acc[j].w * ar1;
    }
    #pragma unroll
    for (int o = 1; o < 4; o <<= 1) {
        #pragma unroll
        for (int hh = 0; hh < 2; hh++) {
            #pragma unroll
            for (int rr = 0; rr < 2; rr++) {
                pel[hh][rr] += __shfl_xor_sync(0xffffffffu, pel[hh][rr], o);
                per[hh][rr] += __shfl_xor_sync(0xffffffffu, per[hh][rr], o);
            }
        }
    }
    if (tig == 0) {
        #pragma unroll
        for (int hh = 0; hh < 2; hh++) {
            int head = warpN * 2 + hh;
            g_el[r0 * HEADS + head] = pel[hh][0];
            g_el[r1 * HEADS + head] = pel[hh][1];
            g_er[r0 * HEADS + head] = per[hh][0];
            g_er[r1 * HEADS + head] = per[hh][1];
        }
    }

    __syncthreads();
    {
        const int lr0 = rowbase + g, lr1 = lr0 + 8;
        #pragma unroll
        for (int j = 0; j < 8; j++) {
            int col = warpN * 64 + j * 8 + 2 * tig;
            *(__half2*)&xs[lr0 * XSTRIDE + col] = __floats2half2_rn(acc[j].x, acc[j].y);
            *(__half2*)&xs[lr1 * XSTRIDE + col] = __floats2half2_rn(acc[j].z, acc[j].w);
        }
    }
    __syncthreads();
    for (int q = tid; q < MTILE * 16; q += 320) {
        int row = q >> 4, c8 = q & 15;
        uint4 v = *(const uint4*)&xs[row * XSTRIDE + c8 * 8];
        ((uint4*)(g_hh + (size_t)(base + row) * F))[c8] = v;
    }
}

// ---------------- fused edge softmax + aggregation (gather, no max pass) ------
__device__ __forceinline__ float leaky_exp(float e) {
    e = e > 0.f ? e : NEG_SLOPE * e;
    return __expf(e);
}
__device__ __forceinline__ void acc_edge(float4& acc, float a, uint2 v) {
    float2 f01 = __half22float2(*(__half2*)&v.x);
    float2 f23 = __half22float2(*(__half2*)&v.y);
    acc.x = fmaf(a, f01.x, acc.x);
    acc.y = fmaf(a, f01.y, acc.y);
    acc.z = fmaf(a, f23.x, acc.z);
    acc.w = fmaf(a, f23.y, acc.w);
}

// LAST=true (final layer): also reset g_cur[node] to 0 for the next call.
template<bool FP16OUT, bool LAST>
__global__ void gat_agg_kernel(const float* __restrict__ bias, float* __restrict__ out,
                               __half* __restrict__ out_h) {
    int node = (blockIdx.x * blockDim.x + threadIdx.x) >> 5;
    int lane = threadIdx.x & 31;
    if (node >= N_NODES) return;

    const size_t start = (size_t)node * CAP;
    int deg = (int)g_cur[node];
    if (deg > CAP) deg = CAP;
    if (LAST && lane == 0) g_cur[node] = 0u;
    const int head = lane >> 3;
    const float erh = g_er[node * 4 + head];
    const __half* __restrict__ hh = g_hh;

    float4 acc = make_float4(0.f, 0.f, 0.f, 0.f);
    float denom = 0.f;
    int i = 0;
    for (; i + 8 <= deg; i += 8) {
        int s[8];
        #pragma unroll
        for (int u = 0; u < 8; u++) s[u] = g_csr_src[start + i + u];
        float a[8];
        uint2 v[8];
        #pragma unroll
        for (int u = 0; u < 8; u++) {
            a[u] = g_el[s[u] * 4 + head];
            v[u] = *(const uint2*)(hh + (size_t)s[u] * F + lane * 4);
        }
        #pragma unroll
        for (int u = 0; u < 8; u++) {
            a[u] = leaky_exp(a[u] + erh);
            denom += a[u];
            acc_edge(acc, a[u], v[u]);
        }
    }
    for (; i < deg; i++) {
        int s0 = g_csr_src[start + i];
        float a0 = leaky_exp(g_el[s0 * 4 + head] + erh);
        uint2 v0 = *(const uint2*)(hh + (size_t)s0 * F + lane * 4);
        denom += a0;
        acc_edge(acc, a0, v0);
    }

    const float inv = 1.0f / fmaxf(denom, 1e-9f);
    const float4 b4 = ((const float4*)bias)[lane];
    float4 r;
    r.x = acc.x * inv + b4.x; r.x = r.x > 0.f ? r.x : expm1f(r.x);
    r.y = acc.y * inv + b4.y; r.y = r.y > 0.f ? r.y : expm1f(r.y);
    r.z = acc.z * inv + b4.z; r.z = r.z > 0.f ? r.z : expm1f(r.z);
    r.w = acc.w * inv + b4.w; r.w = r.w > 0.f ? r.w : expm1f(r.w);

    if (FP16OUT) {
        uint2 u;
        u.x = pack_h2(r.x, r.y); u.y = pack_h2(r.z, r.w);
        *(uint2*)(out_h + (size_t)node * F + lane * 4) = u;
    } else {
        *(float4*)(out + (size_t)node * F + lane * 4) = r;
    }
}

// ---------------- host orchestration -----------------------------------------

extern "C" void kernel_launch(void* const* d_in, const int* in_sizes, int n_in,
                              void* d_out, int out_size) {
    const float* features = (const float*)d_in[0];
    const int*   src      = (const int*)  d_in[1];
    const int*   dst      = (const int*)  d_in[2];
    const float* W1       = (const float*)d_in[3];
    const float* al1      = (const float*)d_in[4];
    const float* ar1      = (const float*)d_in[5];
    const float* b1       = (const float*)d_in[6];
    const float* W2       = (const float*)d_in[7];
    const float* al2      = (const float*)d_in[8];
    const float* ar2      = (const float*)d_in[9];
    const float* b2       = (const float*)d_in[10];
    float* out = (float*)d_out;

    __half* xh = nullptr;  cudaGetSymbolAddress((void**)&xh,  g_xh);
    __half* x2h = nullptr; cudaGetSymbolAddress((void**)&x2h, g_x2h);

    // slot 4 = gemm1 (ncu capture target)
    conv_half_kernel<<<(N_NODES * F / 4 + 255) / 256, 256>>>(features);   // 1
    bfrag_kernel<<<8, 256>>>(W1);                                         // 2
    scatter_kernel<<<(N_EDGES + 255) / 256, 256>>>(src, dst);             // 3
    gemm_mma_kernel<<<N_NODES / MTILE, 320>>>(xh, al1, ar1);              // 4 <- profiled
    gat_agg_kernel<true, false><<<(N_NODES * 32 + 255) / 256, 256>>>(b1, nullptr, x2h); // 5
    bfrag_kernel<<<8, 256>>>(W2);                                         // 6
    gemm_mma_kernel<<<N_NODES / MTILE, 320>>>(x2h, al2, ar2);             // 7
    gat_agg_kernel<false, true><<<(N_NODES * 32 + 255) / 256, 256>>>(b2, out, nullptr); // 8
}

// round 13
// speedup vs baseline: 1.5424x; 1.5424x over previous
#include <cuda_runtime.h>
#include <cuda_fp16.h>
#include <math.h>
#include <stdint.h>

#define N_NODES 50000
#define N_EDGES 800000
#define F       128      // HEADS*HID
#define HEADS   4
#define HID     32
#define NEG_SLOPE 0.2f
#define MTILE   80       // 50000 = 625 * 80
#define SCAN_BLK 512
#define NSCAN ((N_NODES + SCAN_BLK - 1) / SCAN_BLK)   // 98

// ---------------- device-global scratch (no allocations allowed) -------------
__device__ __align__(16) __half g_hh [N_NODES * F];   // h = x @ W (fp16)
__device__ __align__(16) __half g_xh [N_NODES * F];   // layer-1 input, fp16
__device__ __align__(16) __half g_x2h[N_NODES * F];   // layer-1 output, fp16
__device__ __align__(16) float  g_el [N_NODES * HEADS];
__device__ __align__(16) float  g_er [N_NODES * HEADS];
__device__ __align__(16) uint4  g_Bfrag[8 * 8 * 32];  // W fp16 fragments (paired n-tiles)
__device__ unsigned g_deg[N_NODES];                    // zero-init; scan3 re-zeroes
__device__ unsigned g_off[N_NODES + 1];
__device__ unsigned g_cur[N_NODES];
__device__ unsigned g_part[NSCAN];
__device__ int      g_csr_src[N_EDGES];               // src ids grouped by dst

// ---------------- helpers -----------------------------------------------------
__device__ __forceinline__ unsigned pack_h2(float x0, float x1) {
    __half2 h = __floats2half2_rn(x0, x1);
    return *(unsigned*)&h;
}
__device__ __forceinline__ void mma_f16(float4& d,
                                        unsigned a0, unsigned a1, unsigned a2, unsigned a3,
                                        unsigned b0, unsigned b1) {
    asm volatile("mma.sync.aligned.m16n8k16.row.col.f32.f16.f16.f32 "
                 "{%0,%1,%2,%3}, {%4,%5,%6,%7}, {%8,%9}, {%0,%1,%2,%3};"
                 : "+f"(d.x), "+f"(d.y), "+f"(d.z), "+f"(d.w)
                 : "r"(a0), "r"(a1), "r"(a2), "r"(a3), "r"(b0), "r"(b1));
}
__device__ __forceinline__ void ldsm_x4(unsigned& a0, unsigned& a1, unsigned& a2, unsigned& a3,
                                        uint32_t addr) {
    asm volatile("ldmatrix.sync.aligned.m8n8.x4.shared.b16 {%0,%1,%2,%3}, [%4];"
                 : "=r"(a0), "=r"(a1), "=r"(a2), "=r"(a3) : "r"(addr));
}

// ---------------- fp32 -> fp16 convert (layer-1 input) ------------------------
__global__ void conv_half_kernel(const float* __restrict__ x) {
    int i = blockIdx.x * blockDim.x + threadIdx.x;
    if (i >= N_NODES * F / 4) return;
    float4 v = ((const float4*)x)[i];
    uint2 u;
    u.x = pack_h2(v.x, v.y); u.y = pack_h2(v.z, v.w);
    ((uint2*)g_xh)[i] = u;
}

// ---------------- CSR build (round-11 known-good path) ------------------------
__global__ void hist_kernel(const int* __restrict__ dst) {
    int e = blockIdx.x * blockDim.x + threadIdx.x;
    if (e < N_EDGES) atomicAdd(&g_deg[dst[e]], 1u);
}

__global__ void scan1_kernel() {        // per-block reduce of g_deg
    __shared__ unsigned s[SCAN_BLK];
    int t = threadIdx.x, i = blockIdx.x * SCAN_BLK + t;
    s[t] = (i < N_NODES) ? g_deg[i] : 0u;
    __syncthreads();
    for (int o = SCAN_BLK / 2; o > 0; o >>= 1) {
        if (t < o) s[t] += s[t + o];
        __syncthreads();
    }
    if (t == 0) g_part[blockIdx.x] = s[0];
}

__global__ void scan2_kernel() {        // scan the 98 partials (1 block)
    __shared__ unsigned s[128];
    int t = threadIdx.x;
    unsigned v = (t < NSCAN) ? g_part[t] : 0u;
    s[t] = v; __syncthreads();
    for (int o = 1; o < 128; o <<= 1) {
        unsigned u = (t >= o) ? s[t - o] : 0u;
        __syncthreads();
        s[t] += u;
        __syncthreads();
    }
    if (t < NSCAN) g_part[t] = s[t] - v;          // exclusive
    if (t == 0) g_off[N_NODES] = N_EDGES;
}

__global__ void scan3_kernel() {        // block scan + base; re-zero g_deg
    __shared__ unsigned s[SCAN_BLK];
    int t = threadIdx.x, i = blockIdx.x * SCAN_BLK + t;
    unsigned v = (i < N_NODES) ? g_deg[i] : 0u;
    s[t] = v; __syncthreads();
    for (int o = 1; o < SCAN_BLK; o <<= 1) {
        unsigned u = (t >= o) ? s[t - o] : 0u;
        __syncthreads();
        s[t] += u;
        __syncthreads();
    }
    if (i < N_NODES) {
        unsigned excl = s[t] - v + g_part[blockIdx.x];
        g_off[i] = excl; g_cur[i] = excl;
        g_deg[i] = 0u;
    }
}

__global__ void scatter_kernel(const int* __restrict__ src, const int* __restrict__ dst) {
    int e = blockIdx.x * blockDim.x + threadIdx.x;
    if (e >= N_EDGES) return;
    unsigned pos = atomicAdd(&g_cur[dst[e]], 1u);
    g_csr_src[pos] = src[e];
}

// ---------------- W -> fp16 fragment layout (m16n8k16, paired n-tiles) --------
__global__ void bfrag_kernel(const float* __restrict__ W) {
    int idx = blockIdx.x * blockDim.x + threadIdx.x;
    if (idx >= 8 * 8 * 32) return;
    int lane = idx & 31, p = (idx >> 5) & 7, kk = idx >> 8;
    int g = lane >> 2, tig = lane & 3;
    int k0 = kk * 16 + 2 * tig;
    int k1 = k0 + 8;
    int n0 = (2 * p) * 8 + g;
    int n1 = (2 * p + 1) * 8 + g;
    uint4 o;
    o.x = pack_h2(W[k0 * 128 + n0], W[(k0 + 1) * 128 + n0]);
    o.y = pack_h2(W[k1 * 128 + n0], W[(k1 + 1) * 128 + n0]);
    o.z = pack_h2(W[k0 * 128 + n1], W[(k0 + 1) * 128 + n1]);
    o.w = pack_h2(W[k1 * 128 + n1], W[(k1 + 1) * 128 + n1]);
    g_Bfrag[idx] = o;
}

// ---------------- tensor-core GEMM (fp16 A via ldmatrix) + fused el/er --------
#define XSTRIDE 136
__global__ __launch_bounds__(320) void gemm_mma_kernel(
        const __half* __restrict__ x,
        const float* __restrict__ al, const float* __restrict__ ar) {
    __shared__ __half xs[MTILE * XSTRIDE];
    const int tid = threadIdx.x, wid = tid >> 5, lane = tid & 31;
    const int g = lane >> 2, tig = lane & 3;
    const int base = blockIdx.x * MTILE;

    for (int q = tid; q < MTILE * 16; q += 320) {
        int row = q >> 4, c8 = q & 15;
        uint4 v = ((const uint4*)(x + (size_t)(base + row) * F))[c8];
        *(uint4*)&xs[row * XSTRIDE + c8 * 8] = v;
    }
    __syncthreads();

    const int warpM = wid >> 1, warpN = wid & 1;
    const int rowbase = warpM * 16;

    const int lrow = rowbase + ((lane >> 3) & 1) * 8 + (lane & 7);
    uint32_t abase = (uint32_t)__cvta_generic_to_shared(xs)
                   + lrow * (XSTRIDE * 2) + (lane >> 4) * 16;

    float4 acc[8];
    #pragma unroll
    for (int j = 0; j < 8; j++) acc[j] = make_float4(0.f, 0.f, 0.f, 0.f);

    #pragma unroll
    for (int kk = 0; kk < 8; kk++) {
        unsigned a0, a1, a2, a3;
        ldsm_x4(a0, a1, a2, a3, abase + kk * 32);
        const uint4* bp = g_Bfrag + (size_t)(kk * 8 + warpN * 4) * 32 + lane;
        #pragma unroll
        for (int jp = 0; jp < 4; jp++) {
            uint4 b = bp[jp * 32];
            mma_f16(acc[2 * jp + 0], a0, a1, a2, a3, b.x, b.y);
            mma_f16(acc[2 * jp + 1], a0, a1, a2, a3, b.z, b.w);
        }
    }

    // ---- epilogue: el/er + smem-staged coalesced h store ----
    const int r0 = base + rowbase + g, r1 = r0 + 8;
    float pel[2][2] = {{0.f,0.f},{0.f,0.f}};
    float per[2][2] = {{0.f,0.f},{0.f,0.f}};
    #pragma unroll
    for (int j = 0; j < 8; j++) {
        int col = warpN * 64 + j * 8 + 2 * tig;
        float al0 = al[col], al1 = al[col + 1];
        float ar0 = ar[col], ar1 = ar[col + 1];
        int hh = j >> 2;
        pel[hh][0] += acc[j].x * al0 + acc[j].y * al1;
        pel[hh][1] += acc[j].z * al0 + acc[j].w * al1;
        per[hh][0] += acc[j].x * ar0 + acc[j].y * ar1;
        per[hh][1] += acc[j].z * ar0 + acc[j].w * ar1;
    }
    #pragma unroll
    for (int o = 1; o < 4; o <<= 1) {
        #pragma unroll
        for (int hh = 0; hh < 2; hh++) {
            #pragma unroll
            for (int rr = 0; rr < 2; rr++) {
                pel[hh][rr] += __shfl_xor_sync(0xffffffffu, pel[hh][rr], o);
                per[hh][rr] += __shfl_xor_sync(0xffffffffu, per[hh][rr], o);
            }
        }
    }
    if (tig == 0) {
        #pragma unroll
        for (int hh = 0; hh < 2; hh++) {
            int head = warpN * 2 + hh;
            g_el[r0 * HEADS + head] = pel[hh][0];
            g_el[r1 * HEADS + head] = pel[hh][1];
            g_er[r0 * HEADS + head] = per[hh][0];
            g_er[r1 * HEADS + head] = per[hh][1];
        }
    }

    __syncthreads();
    {
        const int lr0 = rowbase + g, lr1 = lr0 + 8;
        #pragma unroll
        for (int j = 0; j < 8; j++) {
            int col = warpN * 64 + j * 8 + 2 * tig;
            *(__half2*)&xs[lr0 * XSTRIDE + col] = __floats2half2_rn(acc[j].x, acc[j].y);
            *(__half2*)&xs[lr1 * XSTRIDE + col] = __floats2half2_rn(acc[j].z, acc[j].w);
        }
    }
    __syncthreads();
    for (int q = tid; q < MTILE * 16; q += 320) {
        int row = q >> 4, c8 = q & 15;
        uint4 v = *(const uint4*)&xs[row * XSTRIDE + c8 * 8];
        ((uint4*)(g_hh + (size_t)(base + row) * F))[c8] = v;
    }
}

// ---------------- fused edge softmax + aggregation ----------------------------
// One warp per dst node; HALF-WARP edge parallelism: lane hl=l&15 owns 8
// features (uint4 of half2s), half A (l<16) takes even edges, half B odd.
// Halves combine at the end via shfl.xor(16).
__device__ __forceinline__ float leaky_exp(float e) {
    e = e > 0.f ? e : NEG_SLOPE * e;
    return __expf(e);
}
__device__ __forceinline__ void acc_edge8(float4& acc0, float4& acc1, float a, uint4 v) {
    float2 f0 = __half22float2(*(__half2*)&v.x);
    float2 f1 = __half22float2(*(__half2*)&v.y);
    float2 f2 = __half22float2(*(__half2*)&v.z);
    float2 f3 = __half22float2(*(__half2*)&v.w);
    acc0.x = fmaf(a, f0.x, acc0.x); acc0.y = fmaf(a, f0.y, acc0.y);
    acc0.z = fmaf(a, f1.x, acc0.z); acc0.w = fmaf(a, f1.y, acc0.w);
    acc1.x = fmaf(a, f2.x, acc1.x); acc1.y = fmaf(a, f2.y, acc1.y);
    acc1.z = fmaf(a, f3.x, acc1.z); acc1.w = fmaf(a, f3.y, acc1.w);
}

template<bool FP16OUT>
__global__ void gat_agg_kernel(const float* __restrict__ bias, float* __restrict__ out,
                               __half* __restrict__ out_h) {
    int node = (blockIdx.x * blockDim.x + threadIdx.x) >> 5;
    int lane = threadIdx.x & 31;
    if (node >= N_NODES) return;

    const unsigned start = g_off[node];
    const int deg = (int)(g_off[node + 1] - start);
    const int hl = lane & 15;           // feature-lane within half-warp
    const int half = lane >> 4;         // 0: even edges, 1: odd edges
    const int head = hl >> 2;           // 8 features/lane -> head = hl/4
    const float erh = g_er[node * 4 + head];
    const __half* __restrict__ hh = g_hh;

    float4 acc0 = make_float4(0.f, 0.f, 0.f, 0.f);
    float4 acc1 = make_float4(0.f, 0.f, 0.f, 0.f);
    float denom = 0.f;

    int i = 0;
    // main: 8 edges per iteration, 4 per half (even/odd interleave)
    for (; i + 8 <= deg; i += 8) {
        int s[4];
        #pragma unroll
        for (int u = 0; u < 4; u++) s[u] = g_csr_src[start + i + 2 * u + half];
        float a[4]; uint4 v[4];
        #pragma unroll
        for (int u = 0; u < 4; u++) {
            a[u] = g_el[s[u] * 4 + head];
            v[u] = *(const uint4*)(hh + (size_t)s[u] * F + hl * 8);
        }
        #pragma unroll
        for (int u = 0; u < 4; u++) {
            float au = leaky_exp(a[u] + erh);
            denom += au;
            acc_edge8(acc0, acc1, au, v[u]);
        }
    }
    // pair tail: 2 edges per iteration, 1 per half
    for (; i + 2 <= deg; i += 2) {
        int s0 = g_csr_src[start + i + half];
        float a0 = leaky_exp(g_el[s0 * 4 + head] + erh);
        uint4 v0 = *(const uint4*)(hh + (size_t)s0 * F + hl * 8);
        denom += a0;
        acc_edge8(acc0, acc1, a0, v0);
    }
    // odd final edge: half A only
    if (i < deg && half == 0) {
        int s0 = g_csr_src[start + i];
        float a0 = leaky_exp(g_el[s0 * 4 + head] + erh);
        uint4 v0 = *(const uint4*)(hh + (size_t)s0 * F + hl * 8);
        denom += a0;
        acc_edge8(acc0, acc1, a0, v0);
    }

    // combine the two halves (xor 16): every lane ends with the full sums
    acc0.x += __shfl_xor_sync(0xffffffffu, acc0.x, 16);
    acc0.y += __shfl_xor_sync(0xffffffffu, acc0.y, 16);
    acc0.z += __shfl_xor_sync(0xffffffffu, acc0.z, 16);
    acc0.w += __shfl_xor_sync(0xffffffffu, acc0.w, 16);
    acc1.x += __shfl_xor_sync(0xffffffffu, acc1.x, 16);
    acc1.y += __shfl_xor_sync(0xffffffffu, acc1.y, 16);
    acc1.z += __shfl_xor_sync(0xffffffffu, acc1.z, 16);
    acc1.w += __shfl_xor_sync(0xffffffffu, acc1.w, 16);
    denom  += __shfl_xor_sync(0xffffffffu, denom, 16);

    if (half == 0) {
        const float inv = 1.0f / fmaxf(denom, 1e-9f);
        const float4 b0 = ((const float4*)bias)[hl * 2];
        const float4 b1 = ((const float4*)bias)[hl * 2 + 1];
        float4 r0, r1;
        r0.x = acc0.x * inv + b0.x; r0.x = r0.x > 0.f ? r0.x : expm1f(r0.x);
        r0.y = acc0.y * inv + b0.y; r0.y = r0.y > 0.f ? r0.y : expm1f(r0.y);
        r0.z = acc0.z * inv + b0.z; r0.z = r0.z > 0.f ? r0.z : expm1f(r0.z);
        r0.w = acc0.w * inv + b0.w; r0.w = r0.w > 0.f ? r0.w : expm1f(r0.w);
        r1.x = acc1.x * inv + b1.x; r1.x = r1.x > 0.f ? r1.x : expm1f(r1.x);
        r1.y = acc1.y * inv + b1.y; r1.y = r1.y > 0.f ? r1.y : expm1f(r1.y);
        r1.z = acc1.z * inv + b1.z; r1.z = r1.z > 0.f ? r1.z : expm1f(r1.z);
        r1.w = acc1.w * inv + b1.w; r1.w = r1.w > 0.f ? r1.w : expm1f(r1.w);

        if (FP16OUT) {
            uint4 u;
            u.x = pack_h2(r0.x, r0.y); u.y = pack_h2(r0.z, r0.w);
            u.z = pack_h2(r1.x, r1.y); u.w = pack_h2(r1.z, r1.w);
            *(uint4*)(out_h + (size_t)node * F + hl * 8) = u;
        } else {
            float* po = out + (size_t)node * F + hl * 8;
            *(float4*)po = r0;
            *(float4*)(po + 4) = r1;
        }
    }
}

// ---------------- host orchestration -----------------------------------------

extern "C" void kernel_launch(void* const* d_in, const int* in_sizes, int n_in,
                              void* d_out, int out_size) {
    const float* features = (const float*)d_in[0];
    const int*   src      = (const int*)  d_in[1];
    const int*   dst      = (const int*)  d_in[2];
    const float* W1       = (const float*)d_in[3];
    const float* al1      = (const float*)d_in[4];
    const float* ar1      = (const float*)d_in[5];
    const float* b1       = (const float*)d_in[6];
    const float* W2       = (const float*)d_in[7];
    const float* al2      = (const float*)d_in[8];
    const float* ar2      = (const float*)d_in[9];
    const float* b2       = (const float*)d_in[10];
    float* out = (float*)d_out;

    __half* xh = nullptr;  cudaGetSymbolAddress((void**)&xh,  g_xh);
    __half* x2h = nullptr; cudaGetSymbolAddress((void**)&x2h, g_x2h);

    // slot 4 = gemm1 (ncu capture target)
    conv_half_kernel<<<(N_NODES * F / 4 + 255) / 256, 256>>>(features);   // 1
    bfrag_kernel<<<8, 256>>>(W1);                                         // 2
    hist_kernel<<<(N_EDGES + 255) / 256, 256>>>(dst);                     // 3
    gemm_mma_kernel<<<N_NODES / MTILE, 320>>>(xh, al1, ar1);              // 4 <- profiled
    scan1_kernel<<<NSCAN, SCAN_BLK>>>();                                  // 5
    scan2_kernel<<<1, 128>>>();                                           // 6
    scan3_kernel<<<NSCAN, SCAN_BLK>>>();                                  // 7
    scatter_kernel<<<(N_EDGES + 255) / 256, 256>>>(src, dst);             // 8
    gat_agg_kernel<true><<<(N_NODES * 32 + 255) / 256, 256>>>(b1, nullptr, x2h);  // 9
    bfrag_kernel<<<8, 256>>>(W2);                                         // 10
    gemm_mma_kernel<<<N_NODES / MTILE, 320>>>(x2h, al2, ar2);             // 11
    gat_agg_kernel<false><<<(N_NODES * 32 + 255) / 256, 256>>>(b2, out, nullptr); // 12
}

// round 16
// speedup vs baseline: 1.5934x; 1.0331x over previous
#include <cuda_runtime.h>
#include <cuda_fp16.h>
#include <math.h>
#include <stdint.h>

#define N_NODES 50000
#define N_EDGES 800000
#define F       128      // HEADS*HID
#define HEADS   4
#define HID     32
#define NEG_SLOPE 0.2f
#define MTILE   80       // 50000 = 625 * 80
#define SCAN_BLK 512
#define NSCAN ((N_NODES + SCAN_BLK - 1) / SCAN_BLK)   // 98

// ---------------- device-global scratch (no allocations allowed) -------------
__device__ __align__(16) __half g_hh [N_NODES * F];   // h = x @ W (fp16)
__device__ __align__(16) __half g_x2h[N_NODES * F];   // layer-1 output, fp16
__device__ __align__(16) float  g_el [N_NODES * HEADS];
__device__ __align__(16) float  g_er [N_NODES * HEADS];
__device__ __align__(16) uint4  g_Bfrag[8 * 8 * 32];  // W fp16 fragments (paired n-tiles)
__device__ unsigned g_deg[N_NODES];                    // zero-init; scan3 re-zeroes
__device__ unsigned g_off[N_NODES + 1];
__device__ unsigned g_cur[N_NODES];
__device__ unsigned g_part[NSCAN];
__device__ int      g_csr_src[N_EDGES];               // src ids grouped by dst

// ---------------- helpers -----------------------------------------------------
__device__ __forceinline__ unsigned pack_h2(float x0, float x1) {
    __half2 h = __floats2half2_rn(x0, x1);
    return *(unsigned*)&h;
}
__device__ __forceinline__ void mma_f16(float4& d,
                                        unsigned a0, unsigned a1, unsigned a2, unsigned a3,
                                        unsigned b0, unsigned b1) {
    asm volatile("mma.sync.aligned.m16n8k16.row.col.f32.f16.f16.f32 "
                 "{%0,%1,%2,%3}, {%4,%5,%6,%7}, {%8,%9}, {%0,%1,%2,%3};"
                 : "+f"(d.x), "+f"(d.y), "+f"(d.z), "+f"(d.w)
                 : "r"(a0), "r"(a1), "r"(a2), "r"(a3), "r"(b0), "r"(b1));
}
__device__ __forceinline__ void ldsm_x4(unsigned& a0, unsigned& a1, unsigned& a2, unsigned& a3,
                                        uint32_t addr) {
    asm volatile("ldmatrix.sync.aligned.m8n8.x4.shared.b16 {%0,%1,%2,%3}, [%4];"
                 : "=r"(a0), "=r"(a1), "=r"(a2), "=r"(a3) : "r"(addr));
}

// ---------------- CSR build ---------------------------------------------------
__global__ void hist_kernel(const int* __restrict__ dst) {
    int e = blockIdx.x * blockDim.x + threadIdx.x;
    if (e < N_EDGES) atomicAdd(&g_deg[dst[e]], 1u);
}

__global__ void scan1_kernel() {        // per-block reduce of g_deg
    __shared__ unsigned s[SCAN_BLK];
    int t = threadIdx.x, i = blockIdx.x * SCAN_BLK + t;
    s[t] = (i < N_NODES) ? g_deg[i] : 0u;
    __syncthreads();
    for (int o = SCAN_BLK / 2; o > 0; o >>= 1) {
        if (t < o) s[t] += s[t + o];
        __syncthreads();
    }
    if (t == 0) g_part[blockIdx.x] = s[0];
}

__global__ void scan2_kernel() {        // scan the 98 partials (1 block)
    __shared__ unsigned s[128];
    int t = threadIdx.x;
    unsigned v = (t < NSCAN) ? g_part[t] : 0u;
    s[t] = v; __syncthreads();
    for (int o = 1; o < 128; o <<= 1) {
        unsigned u = (t >= o) ? s[t - o] : 0u;
        __syncthreads();
        s[t] += u;
        __syncthreads();
    }
    if (t < NSCAN) g_part[t] = s[t] - v;          // exclusive
    if (t == 0) g_off[N_NODES] = N_EDGES;
}

__global__ void scan3_kernel() {        // block scan + base; re-zero g_deg
    __shared__ unsigned s[SCAN_BLK];
    int t = threadIdx.x, i = blockIdx.x * SCAN_BLK + t;
    unsigned v = (i < N_NODES) ? g_deg[i] : 0u;
    s[t] = v; __syncthreads();
    for (int o = 1; o < SCAN_BLK; o <<= 1) {
        unsigned u = (t >= o) ? s[t - o] : 0u;
        __syncthreads();
        s[t] += u;
        __syncthreads();
    }
    if (i < N_NODES) {
        unsigned excl = s[t] - v + g_part[blockIdx.x];
        g_off[i] = excl; g_cur[i] = excl;
        g_deg[i] = 0u;
    }
}

__global__ void scatter_kernel(const int* __restrict__ src, const int* __restrict__ dst) {
    int e = blockIdx.x * blockDim.x + threadIdx.x;
    if (e >= N_EDGES) return;
    unsigned pos = atomicAdd(&g_cur[dst[e]], 1u);
    g_csr_src[pos] = src[e];
}

// ---------------- W -> fp16 fragment layout (m16n8k16, paired n-tiles) --------
__global__ void bfrag_kernel(const float* __restrict__ W) {
    int idx = blockIdx.x * blockDim.x + threadIdx.x;
    if (idx >= 8 * 8 * 32) return;
    int lane = idx & 31, p = (idx >> 5) & 7, kk = idx >> 8;
    int g = lane >> 2, tig = lane & 3;
    int k0 = kk * 16 + 2 * tig;
    int k1 = k0 + 8;
    int n0 = (2 * p) * 8 + g;
    int n1 = (2 * p + 1) * 8 + g;
    uint4 o;
    o.x = pack_h2(W[k0 * 128 + n0], W[(k0 + 1) * 128 + n0]);
    o.y = pack_h2(W[k1 * 128 + n0], W[(k1 + 1) * 128 + n0]);
    o.z = pack_h2(W[k0 * 128 + n1], W[(k0 + 1) * 128 + n1]);
    o.w = pack_h2(W[k1 * 128 + n1], W[(k1 + 1) * 128 + n1]);
    g_Bfrag[idx] = o;
}

// ---------------- tensor-core GEMM + fused el/er ------------------------------
// Templated on input type: layer 1 reads fp32 features and converts during
// smem staging (removes the separate conv pass); layer 2 reads fp16.
#define XSTRIDE 136
template<bool IN_FP32>
__global__ __launch_bounds__(320) void gemm_mma_kernel(
        const void* __restrict__ xin,
        const float* __restrict__ al, const float* __restrict__ ar) {
    __shared__ __half xs[MTILE * XSTRIDE];
    const int tid = threadIdx.x, wid = tid >> 5, lane = tid & 31;
    const int g = lane >> 2, tig = lane & 3;
    const int base = blockIdx.x * MTILE;

    if (IN_FP32) {
        const float* x = (const float*)xin;
        for (int q = tid; q < MTILE * 16; q += 320) {
            int row = q >> 4, c8 = q & 15;
            const float4* px = (const float4*)(x + (size_t)(base + row) * F + c8 * 8);
            float4 v0 = px[0], v1 = px[1];
            uint4 u;
            u.x = pack_h2(v0.x, v0.y); u.y = pack_h2(v0.z, v0.w);
            u.z = pack_h2(v1.x, v1.y); u.w = pack_h2(v1.z, v1.w);
            *(uint4*)&xs[row * XSTRIDE + c8 * 8] = u;
        }
    } else {
        const __half* x = (const __half*)xin;
        for (int q = tid; q < MTILE * 16; q += 320) {
            int row = q >> 4, c8 = q & 15;
            uint4 v = ((const uint4*)(x + (size_t)(base + row) * F))[c8];
            *(uint4*)&xs[row * XSTRIDE + c8 * 8] = v;
        }
    }
    __syncthreads();

    const int warpM = wid >> 1, warpN = wid & 1;
    const int rowbase = warpM * 16;

    const int lrow = rowbase + ((lane >> 3) & 1) * 8 + (lane & 7);
    uint32_t abase = (uint32_t)__cvta_generic_to_shared(xs)
                   + lrow * (XSTRIDE * 2) + (lane >> 4) * 16;

    float4 acc[8];
    #pragma unroll
    for (int j = 0; j < 8; j++) acc[j] = make_float4(0.f, 0.f, 0.f, 0.f);

    #pragma unroll
    for (int kk = 0; kk < 8; kk++) {
        unsigned a0, a1, a2, a3;
        ldsm_x4(a0, a1, a2, a3, abase + kk * 32);
        const uint4* bp = g_Bfrag + (size_t)(kk * 8 + warpN * 4) * 32 + lane;
        #pragma unroll
        for (int jp = 0; jp < 4; jp++) {
            uint4 b = bp[jp * 32];
            mma_f16(acc[2 * jp + 0], a0, a1, a2, a3, b.x, b.y);
            mma_f16(acc[2 * jp + 1], a0, a1, a2, a3, b.z, b.w);
        }
    }

    // ---- epilogue: el/er + smem-staged coalesced h store ----
    const int r0 = base + rowbase + g, r1 = r0 + 8;
    float pel[2][2] = {{0.f,0.f},{0.f,0.f}};
    float per[2][2] = {{0.f,0.f},{0.f,0.f}};
    #pragma unroll
    for (int j = 0; j < 8; j++) {
        int col = warpN * 64 + j * 8 + 2 * tig;
        float al0 = al[col], al1 = al[col + 1];
        float ar0 = ar[col], ar1 = ar[col + 1];
        int hh = j >> 2;
        pel[hh][0] += acc[j].x * al0 + acc[j].y * al1;
        pel[hh][1] += acc[j].z * al0 + acc[j].w * al1;
        per[hh][0] += acc[j].x * ar0 + acc[j].y * ar1;
        per[hh][1] += acc[j].z * ar0 + acc[j].w * ar1;
    }
    #pragma unroll
    for (int o = 1; o < 4; o <<= 1) {
        #pragma unroll
        for (int hh = 0; hh < 2; hh++) {
            #pragma unroll
            for (int rr = 0; rr < 2; rr++) {
                pel[hh][rr] += __shfl_xor_sync(0xffffffffu, pel[hh][rr], o);
                per[hh][rr] += __shfl_xor_sync(0xffffffffu, per[hh][rr], o);
            }
        }
    }
    if (tig == 0) {
        #pragma unroll
        for (int hh = 0; hh < 2; hh++) {
            int head = warpN * 2 + hh;
            g_el[r0 * HEADS + head] = pel[hh][0];
            g_el[r1 * HEADS + head] = pel[hh][1];
            g_er[r0 * HEADS + head] = per[hh][0];
            g_er[r1 * HEADS + head] = per[hh][1];
        }
    }

    __syncthreads();
    {
        const int lr0 = rowbase + g, lr1 = lr0 + 8;
        #pragma unroll
        for (int j = 0; j < 8; j++) {
            int col = warpN * 64 + j * 8 + 2 * tig;
            *(__half2*)&xs[lr0 * XSTRIDE + col] = __floats2half2_rn(acc[j].x, acc[j].y);
            *(__half2*)&xs[lr1 * XSTRIDE + col] = __floats2half2_rn(acc[j].z, acc[j].w);
        }
    }
    __syncthreads();
    for (int q = tid; q < MTILE * 16; q += 320) {
        int row = q >> 4, c8 = q & 15;
        uint4 v = *(const uint4*)&xs[row * XSTRIDE + c8 * 8];
        ((uint4*)(g_hh + (size_t)(base + row) * F))[c8] = v;
    }
}

// ---------------- fused edge softmax + aggregation ----------------------------
// One warp per dst node; half-warp edge parallelism (lane hl owns 8 features,
// halves take even/odd edges, combined via shfl.xor(16)). 16-edge main chunk
// keeps 8 gathers in flight per half-lane.
__device__ __forceinline__ float leaky_exp(float e) {
    e = e > 0.f ? e : NEG_SLOPE * e;
    return __expf(e);
}
__device__ __forceinline__ void acc_edge8(float4& acc0, float4& acc1, float a, uint4 v) {
    float2 f0 = __half22float2(*(__half2*)&v.x);
    float2 f1 = __half22float2(*(__half2*)&v.y);
    float2 f2 = __half22float2(*(__half2*)&v.z);
    float2 f3 = __half22float2(*(__half2*)&v.w);
    acc0.x = fmaf(a, f0.x, acc0.x); acc0.y = fmaf(a, f0.y, acc0.y);
    acc0.z = fmaf(a, f1.x, acc0.z); acc0.w = fmaf(a, f1.y, acc0.w);
    acc1.x = fmaf(a, f2.x, acc1.x); acc1.y = fmaf(a, f2.y, acc1.y);
    acc1.z = fmaf(a, f3.x, acc1.z); acc1.w = fmaf(a, f3.y, acc1.w);
}

template<bool FP16OUT>
__global__ void gat_agg_kernel(const float* __restrict__ bias, float* __restrict__ out,
                               __half* __restrict__ out_h) {
    int node = (blockIdx.x * blockDim.x + threadIdx.x) >> 5;
    int lane = threadIdx.x & 31;
    if (node >= N_NODES) return;

    const unsigned start = g_off[node];
    const int deg = (int)(g_off[node + 1] - start);
    const int hl = lane & 15;
    const int half = lane >> 4;
    const int head = hl >> 2;
    const float erh = g_er[node * 4 + head];
    const __half* __restrict__ hh = g_hh;

    float4 acc0 = make_float4(0.f, 0.f, 0.f, 0.f);
    float4 acc1 = make_float4(0.f, 0.f, 0.f, 0.f);
    float denom = 0.f;

    int i = 0;
    // 16-edge chunks: 8 per half in flight
    for (; i + 16 <= deg; i += 16) {
        int s[8];
        #pragma unroll
        for (int u = 0; u < 8; u++) s[u] = g_csr_src[start + i + 2 * u + half];
        float a[8]; uint4 v[8];
        #pragma unroll
        for (int u = 0; u < 8; u++) {
            a[u] = g_el[s[u] * 4 + head];
            v[u] = *(const uint4*)(hh + (size_t)s[u] * F + hl * 8);
        }
        #pragma unroll
        for (int u = 0; u < 8; u++) {
            float au = leaky_exp(a[u] + erh);
            denom += au;
            acc_edge8(acc0, acc1, au, v[u]);
        }
    }
    // 8-edge chunk
    for (; i + 8 <= deg; i += 8) {
        int s[4];
        #pragma unroll
        for (int u = 0; u < 4; u++) s[u] = g_csr_src[start + i + 2 * u + half];
        float a[4]; uint4 v[4];
        #pragma unroll
        for (int u = 0; u < 4; u++) {
            a[u] = g_el[s[u] * 4 + head];
            v[u] = *(const uint4*)(hh + (size_t)s[u] * F + hl * 8);
        }
        #pragma unroll
        for (int u = 0; u < 4; u++) {
            float au = leaky_exp(a[u] + erh);
            denom += au;
            acc_edge8(acc0, acc1, au, v[u]);
        }
    }
    // pair tail
    for (; i + 2 <= deg; i += 2) {
        int s0 = g_csr_src[start + i + half];
        float a0 = leaky_exp(g_el[s0 * 4 + head] + erh);
        uint4 v0 = *(const uint4*)(hh + (size_t)s0 * F + hl * 8);
        denom += a0;
        acc_edge8(acc0, acc1, a0, v0);
    }
    // odd final edge: half A only
    if (i < deg && half == 0) {
        int s0 = g_csr_src[start + i];
        float a0 = leaky_exp(g_el[s0 * 4 + head] + erh);
        uint4 v0 = *(const uint4*)(hh + (size_t)s0 * F + hl * 8);
        denom += a0;
        acc_edge8(acc0, acc1, a0, v0);
    }

    acc0.x += __shfl_xor_sync(0xffffffffu, acc0.x, 16);
    acc0.y += __shfl_xor_sync(0xffffffffu, acc0.y, 16);
    acc0.z += __shfl_xor_sync(0xffffffffu, acc0.z, 16);
    acc0.w += __shfl_xor_sync(0xffffffffu, acc0.w, 16);
    acc1.x += __shfl_xor_sync(0xffffffffu, acc1.x, 16);
    acc1.y += __shfl_xor_sync(0xffffffffu, acc1.y, 16);
    acc1.z += __shfl_xor_sync(0xffffffffu, acc1.z, 16);
    acc1.w += __shfl_xor_sync(0xffffffffu, acc1.w, 16);
    denom  += __shfl_xor_sync(0xffffffffu, denom, 16);

    if (half == 0) {
        const float inv = 1.0f / fmaxf(denom, 1e-9f);
        const float4 b0 = ((const float4*)bias)[hl * 2];
        const float4 b1 = ((const float4*)bias)[hl * 2 + 1];
        float4 r0, r1;
        r0.x = acc0.x * inv + b0.x; r0.x = r0.x > 0.f ? r0.x : expm1f(r0.x);
        r0.y = acc0.y * inv + b0.y; r0.y = r0.y > 0.f ? r0.y : expm1f(r0.y);
        r0.z = acc0.z * inv + b0.z; r0.z = r0.z > 0.f ? r0.z : expm1f(r0.z);
        r0.w = acc0.w * inv + b0.w; r0.w = r0.w > 0.f ? r0.w : expm1f(r0.w);
        r1.x = acc1.x * inv + b1.x; r1.x = r1.x > 0.f ? r1.x : expm1f(r1.x);
        r1.y = acc1.y * inv + b1.y; r1.y = r1.y > 0.f ? r1.y : expm1f(r1.y);
        r1.z = acc1.z * inv + b1.z; r1.z = r1.z > 0.f ? r1.z : expm1f(r1.z);
        r1.w = acc1.w * inv + b1.w; r1.w = r1.w > 0.f ? r1.w : expm1f(r1.w);

        if (FP16OUT) {
            uint4 u;
            u.x = pack_h2(r0.x, r0.y); u.y = pack_h2(r0.z, r0.w);
            u.z = pack_h2(r1.x, r1.y); u.w = pack_h2(r1.z, r1.w);
            *(uint4*)(out_h + (size_t)node * F + hl * 8) = u;
        } else {
            float* po = out + (size_t)node * F + hl * 8;
            *(float4*)po = r0;
            *(float4*)(po + 4) = r1;
        }
    }
}

// ---------------- host orchestration -----------------------------------------

extern "C" void kernel_launch(void* const* d_in, const int* in_sizes, int n_in,
                              void* d_out, int out_size) {
    const float* features = (const float*)d_in[0];
    const int*   src      = (const int*)  d_in[1];
    const int*   dst      = (const int*)  d_in[2];
    const float* W1       = (const float*)d_in[3];
    const float* al1      = (const float*)d_in[4];
    const float* ar1      = (const float*)d_in[5];
    const float* b1       = (const float*)d_in[6];
    const float* W2       = (const float*)d_in[7];
    const float* al2      = (const float*)d_in[8];
    const float* ar2      = (const float*)d_in[9];
    const float* b2       = (const float*)d_in[10];
    float* out = (float*)d_out;

    __half* x2h = nullptr; cudaGetSymbolAddress((void**)&x2h, g_x2h);

    // slot 4 = gemm1 (ncu capture target)
    bfrag_kernel<<<8, 256>>>(W1);                                         // 1
    hist_kernel<<<(N_EDGES + 255) / 256, 256>>>(dst);                     // 2
    scan1_kernel<<<NSCAN, SCAN_BLK>>>();                                  // 3
    gemm_mma_kernel<true><<<N_NODES / MTILE, 320>>>(features, al1, ar1);  // 4 <- profiled
    scan2_kernel<<<1, 128>>>();                                           // 5
    scan3_kernel<<<NSCAN, SCAN_BLK>>>();                                  // 6
    scatter_kernel<<<(N_EDGES + 255) / 256, 256>>>(src, dst);             // 7
    gat_agg_kernel<true><<<(N_NODES * 32 + 255) / 256, 256>>>(b1, nullptr, x2h);  // 8
    bfrag_kernel<<<8, 256>>>(W2);                                         // 9
    gemm_mma_kernel<false><<<N_NODES / MTILE, 320>>>(x2h, al2, ar2);      // 10
    gat_agg_kernel<false><<<(N_NODES * 32 + 255) / 256, 256>>>(b2, out, nullptr); // 11
}

// round 17
// speedup vs baseline: 1.6476x; 1.0340x over previous
#include <cuda_runtime.h>
#include <cuda_fp16.h>
#include <math.h>
#include <stdint.h>

#define N_NODES 50000
#define N_EDGES 800000
#define F       128      // HEADS*HID
#define HEADS   4
#define HID     32
#define NEG_SLOPE 0.2f
#define MTILE   80       // 50000 = 625 * 80
#define SCAN_BLK 512
#define NSCAN ((N_NODES + SCAN_BLK - 1) / SCAN_BLK)   // 98

// ---------------- device-global scratch (no allocations allowed) -------------
__device__ __align__(16) __half g_hh [N_NODES * F];   // h = x @ W (fp16)
__device__ __align__(16) __half g_x2h[N_NODES * F];   // layer-1 output, fp16
__device__ __align__(16) float  g_el [N_NODES * HEADS];
__device__ __align__(16) float  g_er [N_NODES * HEADS];
__device__ __align__(16) uint4  g_Bfrag[8 * 8 * 32];  // W fp16 fragments (paired n-tiles)
__device__ unsigned g_deg[N_NODES];                    // zero-init; scan3 re-zeroes
__device__ unsigned g_off[N_NODES + 1];
__device__ unsigned g_cur[N_NODES];
__device__ unsigned g_part[NSCAN];
__device__ int      g_csr_src[N_EDGES];               // src ids grouped by dst

// ---------------- helpers -----------------------------------------------------
__device__ __forceinline__ unsigned pack_h2(float x0, float x1) {
    __half2 h = __floats2half2_rn(x0, x1);
    return *(unsigned*)&h;
}
__device__ __forceinline__ void mma_f16(float4& d,
                                        unsigned a0, unsigned a1, unsigned a2, unsigned a3,
                                        unsigned b0, unsigned b1) {
    asm volatile("mma.sync.aligned.m16n8k16.row.col.f32.f16.f16.f32 "
                 "{%0,%1,%2,%3}, {%4,%5,%6,%7}, {%8,%9}, {%0,%1,%2,%3};"
                 : "+f"(d.x), "+f"(d.y), "+f"(d.z), "+f"(d.w)
                 : "r"(a0), "r"(a1), "r"(a2), "r"(a3), "r"(b0), "r"(b1));
}
__device__ __forceinline__ void ldsm_x4(unsigned& a0, unsigned& a1, unsigned& a2, unsigned& a3,
                                        uint32_t addr) {
    asm volatile("ldmatrix.sync.aligned.m8n8.x4.shared.b16 {%0,%1,%2,%3}, [%4];"
                 : "=r"(a0), "=r"(a1), "=r"(a2), "=r"(a3) : "r"(addr));
}

// ---------------- CSR build ---------------------------------------------------
__global__ void hist_kernel(const int* __restrict__ dst) {
    int e = blockIdx.x * blockDim.x + threadIdx.x;
    if (e < N_EDGES) atomicAdd(&g_deg[dst[e]], 1u);
}

__global__ void scan1_kernel() {        // per-block reduce of g_deg
    __shared__ unsigned s[SCAN_BLK];
    int t = threadIdx.x, i = blockIdx.x * SCAN_BLK + t;
    s[t] = (i < N_NODES) ? g_deg[i] : 0u;
    __syncthreads();
    for (int o = SCAN_BLK / 2; o > 0; o >>= 1) {
        if (t < o) s[t] += s[t + o];
        __syncthreads();
    }
    if (t == 0) g_part[blockIdx.x] = s[0];
}

__global__ void scan2_kernel() {        // scan the 98 partials (1 block)
    __shared__ unsigned s[128];
    int t = threadIdx.x;
    unsigned v = (t < NSCAN) ? g_part[t] : 0u;
    s[t] = v; __syncthreads();
    for (int o = 1; o < 128; o <<= 1) {
        unsigned u = (t >= o) ? s[t - o] : 0u;
        __syncthreads();
        s[t] += u;
        __syncthreads();
    }
    if (t < NSCAN) g_part[t] = s[t] - v;          // exclusive
    if (t == 0) g_off[N_NODES] = N_EDGES;
}

__global__ void scan3_kernel() {        // block scan + base; re-zero g_deg
    __shared__ unsigned s[SCAN_BLK];
    int t = threadIdx.x, i = blockIdx.x * SCAN_BLK + t;
    unsigned v = (i < N_NODES) ? g_deg[i] : 0u;
    s[t] = v; __syncthreads();
    for (int o = 1; o < SCAN_BLK; o <<= 1) {
        unsigned u = (t >= o) ? s[t - o] : 0u;
        __syncthreads();
        s[t] += u;
        __syncthreads();
    }
    if (i < N_NODES) {
        unsigned excl = s[t] - v + g_part[blockIdx.x];
        g_off[i] = excl; g_cur[i] = excl;
        g_deg[i] = 0u;
    }
}

__global__ void scatter_kernel(const int* __restrict__ src, const int* __restrict__ dst) {
    int e = blockIdx.x * blockDim.x + threadIdx.x;
    if (e >= N_EDGES) return;
    unsigned pos = atomicAdd(&g_cur[dst[e]], 1u);
    g_csr_src[pos] = src[e];
}

// ---------------- W -> fp16 fragment layout (m16n8k16, paired n-tiles) --------
__global__ void bfrag_kernel(const float* __restrict__ W) {
    int idx = blockIdx.x * blockDim.x + threadIdx.x;
    if (idx >= 8 * 8 * 32) return;
    int lane = idx & 31, p = (idx >> 5) & 7, kk = idx >> 8;
    int g = lane >> 2, tig = lane & 3;
    int k0 = kk * 16 + 2 * tig;
    int k1 = k0 + 8;
    int n0 = (2 * p) * 8 + g;
    int n1 = (2 * p + 1) * 8 + g;
    uint4 o;
    o.x = pack_h2(W[k0 * 128 + n0], W[(k0 + 1) * 128 + n0]);
    o.y = pack_h2(W[k1 * 128 + n0], W[(k1 + 1) * 128 + n0]);
    o.z = pack_h2(W[k0 * 128 + n1], W[(k0 + 1) * 128 + n1]);
    o.w = pack_h2(W[k1 * 128 + n1], W[(k1 + 1) * 128 + n1]);
    g_Bfrag[idx] = o;
}

// ---------------- tensor-core GEMM + fused el/er ------------------------------
#define XSTRIDE 136
template<bool IN_FP32>
__global__ __launch_bounds__(320) void gemm_mma_kernel(
        const void* __restrict__ xin,
        const float* __restrict__ al, const float* __restrict__ ar) {
    __shared__ __half xs[MTILE * XSTRIDE];
    const int tid = threadIdx.x, wid = tid >> 5, lane = tid & 31;
    const int g = lane >> 2, tig = lane & 3;
    const int base = blockIdx.x * MTILE;

    if (IN_FP32) {
        const float* x = (const float*)xin;
        for (int q = tid; q < MTILE * 16; q += 320) {
            int row = q >> 4, c8 = q & 15;
            const float4* px = (const float4*)(x + (size_t)(base + row) * F + c8 * 8);
            float4 v0 = px[0], v1 = px[1];
            uint4 u;
            u.x = pack_h2(v0.x, v0.y); u.y = pack_h2(v0.z, v0.w);
            u.z = pack_h2(v1.x, v1.y); u.w = pack_h2(v1.z, v1.w);
            *(uint4*)&xs[row * XSTRIDE + c8 * 8] = u;
        }
    } else {
        const __half* x = (const __half*)xin;
        for (int q = tid; q < MTILE * 16; q += 320) {
            int row = q >> 4, c8 = q & 15;
            uint4 v = ((const uint4*)(x + (size_t)(base + row) * F))[c8];
            *(uint4*)&xs[row * XSTRIDE + c8 * 8] = v;
        }
    }
    __syncthreads();

    const int warpM = wid >> 1, warpN = wid & 1;
    const int rowbase = warpM * 16;

    const int lrow = rowbase + ((lane >> 3) & 1) * 8 + (lane & 7);
    uint32_t abase = (uint32_t)__cvta_generic_to_shared(xs)
                   + lrow * (XSTRIDE * 2) + (lane >> 4) * 16;

    float4 acc[8];
    #pragma unroll
    for (int j = 0; j < 8; j++) acc[j] = make_float4(0.f, 0.f, 0.f, 0.f);

    #pragma unroll
    for (int kk = 0; kk < 8; kk++) {
        unsigned a0, a1, a2, a3;
        ldsm_x4(a0, a1, a2, a3, abase + kk * 32);
        const uint4* bp = g_Bfrag + (size_t)(kk * 8 + warpN * 4) * 32 + lane;
        #pragma unroll
        for (int jp = 0; jp < 4; jp++) {
            uint4 b = bp[jp * 32];
            mma_f16(acc[2 * jp + 0], a0, a1, a2, a3, b.x, b.y);
            mma_f16(acc[2 * jp + 1], a0, a1, a2, a3, b.z, b.w);
        }
    }

    // ---- epilogue: el/er + smem-staged coalesced h store ----
    const int r0 = base + rowbase + g, r1 = r0 + 8;
    float pel[2][2] = {{0.f,0.f},{0.f,0.f}};
    float per[2][2] = {{0.f,0.f},{0.f,0.f}};
    #pragma unroll
    for (int j = 0; j < 8; j++) {
        int col = warpN * 64 + j * 8 + 2 * tig;
        float al0 = al[col], al1 = al[col + 1];
        float ar0 = ar[col], ar1 = ar[col + 1];
        int hh = j >> 2;
        pel[hh][0] += acc[j].x * al0 + acc[j].y * al1;
        pel[hh][1] += acc[j].z * al0 + acc[j].w * al1;
        per[hh][0] += acc[j].x * ar0 + acc[j].y * ar1;
        per[hh][1] += acc[j].z * ar0 + acc[j].w * ar1;
    }
    #pragma unroll
    for (int o = 1; o < 4; o <<= 1) {
        #pragma unroll
        for (int hh = 0; hh < 2; hh++) {
            #pragma unroll
            for (int rr = 0; rr < 2; rr++) {
                pel[hh][rr] += __shfl_xor_sync(0xffffffffu, pel[hh][rr], o);
                per[hh][rr] += __shfl_xor_sync(0xffffffffu, per[hh][rr], o);
            }
        }
    }
    if (tig == 0) {
        #pragma unroll
        for (int hh = 0; hh < 2; hh++) {
            int head = warpN * 2 + hh;
            g_el[r0 * HEADS + head] = pel[hh][0];
            g_el[r1 * HEADS + head] = pel[hh][1];
            g_er[r0 * HEADS + head] = per[hh][0];
            g_er[r1 * HEADS + head] = per[hh][1];
        }
    }

    __syncthreads();
    {
        const int lr0 = rowbase + g, lr1 = lr0 + 8;
        #pragma unroll
        for (int j = 0; j < 8; j++) {
            int col = warpN * 64 + j * 8 + 2 * tig;
            *(__half2*)&xs[lr0 * XSTRIDE + col] = __floats2half2_rn(acc[j].x, acc[j].y);
            *(__half2*)&xs[lr1 * XSTRIDE + col] = __floats2half2_rn(acc[j].z, acc[j].w);
        }
    }
    __syncthreads();
    for (int q = tid; q < MTILE * 16; q += 320) {
        int row = q >> 4, c8 = q & 15;
        uint4 v = *(const uint4*)&xs[row * XSTRIDE + c8 * 8];
        ((uint4*)(g_hh + (size_t)(base + row) * F))[c8] = v;
    }
}

// ---------------- fused edge softmax + aggregation ----------------------------
__device__ __forceinline__ float leaky_exp(float e) {
    e = e > 0.f ? e : NEG_SLOPE * e;
    return __expf(e);
}
__device__ __forceinline__ void acc_edge8(float4& acc0, float4& acc1, float a, uint4 v) {
    float2 f0 = __half22float2(*(__half2*)&v.x);
    float2 f1 = __half22float2(*(__half2*)&v.y);
    float2 f2 = __half22float2(*(__half2*)&v.z);
    float2 f3 = __half22float2(*(__half2*)&v.w);
    acc0.x = fmaf(a, f0.x, acc0.x); acc0.y = fmaf(a, f0.y, acc0.y);
    acc0.z = fmaf(a, f1.x, acc0.z); acc0.w = fmaf(a, f1.y, acc0.w);
    acc1.x = fmaf(a, f2.x, acc1.x); acc1.y = fmaf(a, f2.y, acc1.y);
    acc1.z = fmaf(a, f3.x, acc1.z); acc1.w = fmaf(a, f3.y, acc1.w);
}

template<bool FP16OUT>
__global__ void gat_agg_kernel(const float* __restrict__ bias, float* __restrict__ out,
                               __half* __restrict__ out_h) {
    int node = (blockIdx.x * blockDim.x + threadIdx.x) >> 5;
    int lane = threadIdx.x & 31;
    if (node >= N_NODES) return;

    const unsigned start = g_off[node];
    const int deg = (int)(g_off[node + 1] - start);
    const int hl = lane & 15;
    const int half = lane >> 4;
    const int head = hl >> 2;
    const float erh = g_er[node * 4 + head];
    const __half* __restrict__ hh = g_hh;

    float4 acc0 = make_float4(0.f, 0.f, 0.f, 0.f);
    float4 acc1 = make_float4(0.f, 0.f, 0.f, 0.f);
    float denom = 0.f;

    int i = 0;
    for (; i + 16 <= deg; i += 16) {
        int s[8];
        #pragma unroll
        for (int u = 0; u < 8; u++) s[u] = g_csr_src[start + i + 2 * u + half];
        float a[8]; uint4 v[8];
        #pragma unroll
        for (int u = 0; u < 8; u++) {
            a[u] = g_el[s[u] * 4 + head];
            v[u] = *(const uint4*)(hh + (size_t)s[u] * F + hl * 8);
        }
        #pragma unroll
        for (int u = 0; u < 8; u++) {
            float au = leaky_exp(a[u] + erh);
            denom += au;
            acc_edge8(acc0, acc1, au, v[u]);
        }
    }
    for (; i + 8 <= deg; i += 8) {
        int s[4];
        #pragma unroll
        for (int u = 0; u < 4; u++) s[u] = g_csr_src[start + i + 2 * u + half];
        float a[4]; uint4 v[4];
        #pragma unroll
        for (int u = 0; u < 4; u++) {
            a[u] = g_el[s[u] * 4 + head];
            v[u] = *(const uint4*)(hh + (size_t)s[u] * F + hl * 8);
        }
        #pragma unroll
        for (int u = 0; u < 4; u++) {
            float au = leaky_exp(a[u] + erh);
            denom += au;
            acc_edge8(acc0, acc1, au, v[u]);
        }
    }
    for (; i + 2 <= deg; i += 2) {
        int s0 = g_csr_src[start + i + half];
        float a0 = leaky_exp(g_el[s0 * 4 + head] + erh);
        uint4 v0 = *(const uint4*)(hh + (size_t)s0 * F + hl * 8);
        denom += a0;
        acc_edge8(acc0, acc1, a0, v0);
    }
    if (i < deg && half == 0) {
        int s0 = g_csr_src[start + i];
        float a0 = leaky_exp(g_el[s0 * 4 + head] + erh);
        uint4 v0 = *(const uint4*)(hh + (size_t)s0 * F + hl * 8);
        denom += a0;
        acc_edge8(acc0, acc1, a0, v0);
    }

    acc0.x += __shfl_xor_sync(0xffffffffu, acc0.x, 16);
    acc0.y += __shfl_xor_sync(0xffffffffu, acc0.y, 16);
    acc0.z += __shfl_xor_sync(0xffffffffu, acc0.z, 16);
    acc0.w += __shfl_xor_sync(0xffffffffu, acc0.w, 16);
    acc1.x += __shfl_xor_sync(0xffffffffu, acc1.x, 16);
    acc1.y += __shfl_xor_sync(0xffffffffu, acc1.y, 16);
    acc1.z += __shfl_xor_sync(0xffffffffu, acc1.z, 16);
    acc1.w += __shfl_xor_sync(0xffffffffu, acc1.w, 16);
    denom  += __shfl_xor_sync(0xffffffffu, denom, 16);

    if (half == 0) {
        const float inv = 1.0f / fmaxf(denom, 1e-9f);
        const float4 b0 = ((const float4*)bias)[hl * 2];
        const float4 b1 = ((const float4*)bias)[hl * 2 + 1];
        float4 r0, r1;
        r0.x = acc0.x * inv + b0.x; r0.x = r0.x > 0.f ? r0.x : expm1f(r0.x);
        r0.y = acc0.y * inv + b0.y; r0.y = r0.y > 0.f ? r0.y : expm1f(r0.y);
        r0.z = acc0.z * inv + b0.z; r0.z = r0.z > 0.f ? r0.z : expm1f(r0.z);
        r0.w = acc0.w * inv + b0.w; r0.w = r0.w > 0.f ? r0.w : expm1f(r0.w);
        r1.x = acc1.x * inv + b1.x; r1.x = r1.x > 0.f ? r1.x : expm1f(r1.x);
        r1.y = acc1.y * inv + b1.y; r1.y = r1.y > 0.f ? r1.y : expm1f(r1.y);
        r1.z = acc1.z * inv + b1.z; r1.z = r1.z > 0.f ? r1.z : expm1f(r1.z);
        r1.w = acc1.w * inv + b1.w; r1.w = r1.w > 0.f ? r1.w : expm1f(r1.w);

        if (FP16OUT) {
            uint4 u;
            u.x = pack_h2(r0.x, r0.y); u.y = pack_h2(r0.z, r0.w);
            u.z = pack_h2(r1.x, r1.y); u.w = pack_h2(r1.z, r1.w);
            *(uint4*)(out_h + (size_t)node * F + hl * 8) = u;
        } else {
            float* po = out + (size_t)node * F + hl * 8;
            *(float4*)po = r0;
            *(float4*)(po + 4) = r1;
        }
    }
}

// ---------------- host orchestration -----------------------------------------
// CSR chain runs on a forked side stream, overlapped with bfrag1+gemm1;
// join (event) before agg1. Streams/events created lazily on the first
// (uncaptured, correctness) call — host objects only, no device allocations.

extern "C" void kernel_launch(void* const* d_in, const int* in_sizes, int n_in,
                              void* d_out, int out_size) {
    const float* features = (const float*)d_in[0];
    const int*   src      = (const int*)  d_in[1];
    const int*   dst      = (const int*)  d_in[2];
    const float* W1       = (const float*)d_in[3];
    const float* al1      = (const float*)d_in[4];
    const float* ar1      = (const float*)d_in[5];
    const float* b1       = (const float*)d_in[6];
    const float* W2       = (const float*)d_in[7];
    const float* al2      = (const float*)d_in[8];
    const float* ar2      = (const float*)d_in[9];
    const float* b2       = (const float*)d_in[10];
    float* out = (float*)d_out;

    __half* x2h = nullptr; cudaGetSymbolAddress((void**)&x2h, g_x2h);

    static cudaStream_t s2 = nullptr;
    static cudaEvent_t evFork = nullptr, evJoin = nullptr;
    if (s2 == nullptr) {
        cudaStreamCreateWithFlags(&s2, cudaStreamNonBlocking);
        cudaEventCreateWithFlags(&evFork, cudaEventDisableTiming);
        cudaEventCreateWithFlags(&evJoin, cudaEventDisableTiming);
    }

    // fork: side stream handles the CSR build
    cudaEventRecord(evFork, 0);
    cudaStreamWaitEvent(s2, evFork, 0);
    hist_kernel<<<(N_EDGES + 255) / 256, 256, 0, s2>>>(dst);
    scan1_kernel<<<NSCAN, SCAN_BLK, 0, s2>>>();
    scan2_kernel<<<1, 128, 0, s2>>>();
    scan3_kernel<<<NSCAN, SCAN_BLK, 0, s2>>>();
    scatter_kernel<<<(N_EDGES + 255) / 256, 256, 0, s2>>>(src, dst);
    cudaEventRecord(evJoin, s2);

    // main stream: feature path layer 1
    bfrag_kernel<<<8, 256>>>(W1);
    gemm_mma_kernel<true><<<N_NODES / MTILE, 320>>>(features, al1, ar1);

    // join: agg1 needs both gemm1 and the CSR
    cudaStreamWaitEvent(0, evJoin, 0);
    gat_agg_kernel<true><<<(N_NODES * 32 + 255) / 256, 256>>>(b1, nullptr, x2h);

    // layer 2
    bfrag_kernel<<<8, 256>>>(W2);
    gemm_mma_kernel<false><<<N_NODES / MTILE, 320>>>(x2h, al2, ar2);
    gat_agg_kernel<false><<<(N_NODES * 32 + 255) / 256, 256>>>(b2, out, nullptr);
}